// round 1
// baseline (speedup 1.0000x reference)
#include <cuda_runtime.h>
#include <cuda_bf16.h>
#include <cstdint>

// Problem constants (fixed shapes)
#define BATCH 2
#define CDIM 128
#define NPIX 65536          // 256*256
#define MCOLS 1024          // NPIX / chunks
#define LAST0 64512         // (chunks-1)*MCOLS
#define NROWBLK 4096        // NPIX/16
#define SCALE_L2 20.6099075f   // 1/(0.07 * ln2)
#define LN2F 0.6931471805599453f

// ---------------- scratch (device globals: no allocations allowed) ----------
__device__ uint4  g_Apack[BATCH * NROWBLK * 8 * 32];   // 33.5 MB, mma A fragments
__device__ uint2  g_Bpack[BATCH * 128 * 8 * 32];       // 512 KB, mma B fragments
__device__ float  g_inv2[BATCH * NPIX];
__device__ float  g_posl2[BATCH * NPIX];               // pos logit in log2 domain
__device__ double g_acc;

// ---------------- helpers ----------------
__device__ __forceinline__ unsigned pack2(float lo, float hi) {
    __nv_bfloat162 h = __floats2bfloat162_rn(lo, hi);
    return *reinterpret_cast<unsigned*>(&h);
}

// exp2 via degree-5 Taylor poly + exponent splice. Exact 1.0 at x==0 (masked entries).
// |x| <= ~21 here, so no range issues. Rel err ~2.4e-6.
__device__ __forceinline__ float exp2p(float x) {
    int   i = __float2int_rn(x);
    float f = x - (float)i;
    float p = 1.3333558146e-3f;
    p = fmaf(p, f, 9.6181291076e-3f);
    p = fmaf(p, f, 5.5504108664e-2f);
    p = fmaf(p, f, 2.4022650696e-1f);
    p = fmaf(p, f, 6.9314718056e-1f);
    p = fmaf(p, f, 1.0f);
    return __int_as_float(__float_as_int(p) + (i << 23));
}

// ---------------- kernel 0: zero accumulator ----------------
__global__ void k_zero() { g_acc = 0.0; }

// ---------------- kernel 1: normalize z1/z2, compute pos (fp32), pack A fragments ----
// Block: 256 threads handles 32 pixels x all 128 channels of one batch.
__global__ void __launch_bounds__(256) k_norm_pack(const float* __restrict__ z1,
                                                   const float* __restrict__ z2) {
    const int b  = blockIdx.y;
    const int p0 = blockIdx.x * 32;
    const int tx = threadIdx.x & 31;   // pixel within tile
    const int ty = threadIdx.x >> 5;   // channel group

    __shared__ float s1[128][33];
    __shared__ float red[3][8][32];
    __shared__ float invsm[32];

    const float* z1b = z1 + (size_t)b * CDIM * NPIX + p0;
    const float* z2b = z2 + (size_t)b * CDIM * NPIX + p0;

    float ss1 = 0.f, ss2 = 0.f, dt = 0.f;
#pragma unroll
    for (int j = 0; j < 16; j++) {
        int c = ty * 16 + j;
        float v1 = z1b[(size_t)c * NPIX + tx];
        float v2 = z2b[(size_t)c * NPIX + tx];
        ss1 = fmaf(v1, v1, ss1);
        ss2 = fmaf(v2, v2, ss2);
        dt  = fmaf(v1, v2, dt);
        s1[c][tx] = v1;
    }
    red[0][ty][tx] = ss1; red[1][ty][tx] = ss2; red[2][ty][tx] = dt;
    __syncthreads();

    if (ty == 0) {
        float a = 0.f, bb = 0.f, d = 0.f;
#pragma unroll
        for (int j = 0; j < 8; j++) { a += red[0][j][tx]; bb += red[1][j][tx]; d += red[2][j][tx]; }
        float inv1 = 1.f / fmaxf(sqrtf(a),  1e-12f);
        float inv2 = 1.f / fmaxf(sqrtf(bb), 1e-12f);
        invsm[tx] = inv1;
        g_inv2 [b * NPIX + p0 + tx] = inv2;
        g_posl2[b * NPIX + p0 + tx] = d * inv1 * inv2 * SCALE_L2;  // pos in log2 domain
    }
    __syncthreads();

    // Pack A into mma fragment order: [(b, rowblock, kstep, lane)] -> uint4 {a0,a1,a2,a3}
    // a0 = A[gid][k0..k0+1], a1 = A[gid+8][k0..], a2 = A[gid][k0+8..], a3 = A[gid+8][k0+8..]
#pragma unroll
    for (int q = 0; q < 2; q++) {
        int wi   = threadIdx.x + q * 256;      // 0..511
        int rbl  = wi >> 8;                    // 0..1 local rowblock
        int rem  = wi & 255;
        int s    = rem >> 5;                   // kstep 0..7
        int lane = rem & 31;
        int gid  = lane >> 2, tig = lane & 3;
        int pl   = rbl * 16 + gid;
        int k0   = s * 16 + tig * 2;
        float i1 = invsm[pl], i2 = invsm[pl + 8];
        uint4 o;
        o.x = pack2(s1[k0    ][pl]     * i1, s1[k0 + 1][pl]     * i1);
        o.y = pack2(s1[k0    ][pl + 8] * i2, s1[k0 + 1][pl + 8] * i2);
        o.z = pack2(s1[k0 + 8][pl]     * i1, s1[k0 + 9][pl]     * i1);
        o.w = pack2(s1[k0 + 8][pl + 8] * i2, s1[k0 + 9][pl + 8] * i2);
        int rb = blockIdx.x * 2 + rbl;
        g_Apack[((b * NROWBLK + rb) * 8 + s) * 32 + lane] = o;
    }
}

// ---------------- kernel 2: pack B fragments (last-chunk z2, normalized, *1/(T ln2)) ----
// B fragment: b0 = {B[k0][n], B[k0+1][n]}, b1 = {B[k0+8][n], B[k0+9][n]}, n = nb*8+gid
__global__ void k_packB(const float* __restrict__ z2) {
    int g = blockIdx.x * 256 + threadIdx.x;       // 0..65535
    int b = g >> 15;
    int r = g & 32767;
    int lane = r & 31;
    int s    = (r >> 5) & 7;
    int nbg  = r >> 8;                            // 0..127
    int gid = lane >> 2, tig = lane & 3;
    int n  = nbg * 8 + gid;
    int pq = LAST0 + n;
    float inv = g_inv2[b * NPIX + pq] * SCALE_L2;
    const float* zp = z2 + (size_t)b * CDIM * NPIX + pq;
    int k0 = s * 16 + tig * 2;
    uint2 o;
    o.x = pack2(zp[(size_t)(k0    ) * NPIX] * inv, zp[(size_t)(k0 + 1) * NPIX] * inv);
    o.y = pack2(zp[(size_t)(k0 + 8) * NPIX] * inv, zp[(size_t)(k0 + 9) * NPIX] * inv);
    g_Bpack[g] = o;
}

// ---------------- kernel 3: GEMM (bf16 mma.sync) + fused masked-softmax epilogue ------
// Block: 8 warps, 128 rows. Each warp owns 16 rows fully (all 1024 cols), A frags in regs.
__global__ void __launch_bounds__(256) k_main(const int* __restrict__ labels) {
    const int b    = blockIdx.y;
    const int row0 = blockIdx.x * 128;
    const int tid  = threadIdx.x;
    const int w    = tid >> 5;
    const int lane = tid & 31;
    const int gid  = lane >> 2, tig = lane & 3;

    __shared__ uint2 Bsm[2048];      // 64 cols x 8 ksteps x 32 lanes
    __shared__ int   labsm[1024];
    __shared__ float warpsum[8];

    for (int i = tid; i < 1024; i += 256)
        labsm[i] = labels[b * NPIX + LAST0 + i];

    // A fragments for this warp's 16 rows, all K: 8 x uint4 = 32 regs
    const int rb = blockIdx.x * 8 + w;
    uint4 a[8];
    const uint4* Ap = g_Apack + ((size_t)(b * NROWBLK + rb) * 8) * 32 + lane;
#pragma unroll
    for (int s = 0; s < 8; s++) a[s] = Ap[s * 32];

    const int r0  = row0 + w * 16 + gid;
    const int lr0 = labels[b * NPIX + r0];
    const int lr1 = labels[b * NPIX + r0 + 8];

    float sx0 = 0.f, se0 = 0.f, sx1 = 0.f, se1 = 0.f;
    const uint2* Bp = g_Bpack + b * 32768;

    for (int it = 0; it < 16; it++) {
        __syncthreads();
#pragma unroll
        for (int i = 0; i < 8; i++)
            Bsm[tid + 256 * i] = Bp[it * 2048 + tid + 256 * i];
        __syncthreads();

#pragma unroll
        for (int nb = 0; nb < 8; nb++) {
            float c0 = 0.f, c1 = 0.f, c2 = 0.f, c3 = 0.f;
#pragma unroll
            for (int s = 0; s < 8; s++) {
                uint2 bf = Bsm[(nb * 8 + s) * 32 + lane];
                asm volatile(
                    "mma.sync.aligned.m16n8k16.row.col.f32.bf16.bf16.f32 "
                    "{%0,%1,%2,%3}, {%4,%5,%6,%7}, {%8,%9}, {%0,%1,%2,%3};\n"
                    : "+f"(c0), "+f"(c1), "+f"(c2), "+f"(c3)
                    : "r"(a[s].x), "r"(a[s].y), "r"(a[s].z), "r"(a[s].w),
                      "r"(bf.x), "r"(bf.y));
            }
            // epilogue: mask (equal labels -> logit 0), accumulate sum_x and sum_exp2
            int n0 = it * 64 + nb * 8 + tig * 2;
            int lc0 = labsm[n0], lc1 = labsm[n0 + 1];
            float v;
            v = (lr0 != lc0) ? c0 : 0.f;  sx0 += v;  se0 += exp2p(v);
            v = (lr0 != lc1) ? c1 : 0.f;  sx0 += v;  se0 += exp2p(v);
            v = (lr1 != lc0) ? c2 : 0.f;  sx1 += v;  se1 += exp2p(v);
            v = (lr1 != lc1) ? c3 : 0.f;  sx1 += v;  se1 += exp2p(v);
        }
    }

    // reduce across the 4 lanes sharing a row (tig dimension)
    sx0 += __shfl_xor_sync(~0u, sx0, 1);  sx0 += __shfl_xor_sync(~0u, sx0, 2);
    se0 += __shfl_xor_sync(~0u, se0, 1);  se0 += __shfl_xor_sync(~0u, se0, 2);
    sx1 += __shfl_xor_sync(~0u, sx1, 1);  sx1 += __shfl_xor_sync(~0u, sx1, 2);
    se1 += __shfl_xor_sync(~0u, se1, 1);  se1 += __shfl_xor_sync(~0u, se1, 2);

    float loss = 0.f;
    if (tig == 0) {
        float p0 = g_posl2[b * NPIX + r0];
        float p1 = g_posl2[b * NPIX + r0 + 8];
        float t0 = se0 + exp2p(p0), x0 = sx0 + p0;
        float t1 = se1 + exp2p(p1), x1 = sx1 + p1;
        // row loss = LSE - mean(x), both converted from log2 to natural units
        loss = LN2F * ((__log2f(t0) - x0 * (1.0f / 1025.0f)) +
                       (__log2f(t1) - x1 * (1.0f / 1025.0f)));
    }
#pragma unroll
    for (int o = 16; o; o >>= 1) loss += __shfl_xor_sync(~0u, loss, o);
    if (lane == 0) warpsum[w] = loss;
    __syncthreads();
    if (tid == 0) {
        float t = 0.f;
#pragma unroll
        for (int i = 0; i < 8; i++) t += warpsum[i];
        atomicAdd(&g_acc, (double)t);
    }
}

// ---------------- kernel 4: finalize ----------------
__global__ void k_finalize(float* out) {
    out[0] = (float)(g_acc / (double)(BATCH * NPIX));
}

// ---------------- launch ----------------
extern "C" void kernel_launch(void* const* d_in, const int* in_sizes, int n_in,
                              void* d_out, int out_size) {
    const float* z1     = (const float*)d_in[0];
    const float* z2     = (const float*)d_in[1];
    const int*   labels = (const int*)d_in[2];
    (void)in_sizes; (void)n_in; (void)out_size;

    k_zero<<<1, 1>>>();
    dim3 g1(NPIX / 32, BATCH);
    k_norm_pack<<<g1, 256>>>(z1, z2);
    k_packB<<<256, 256>>>(z2);
    dim3 g2(NPIX / 128, BATCH);
    k_main<<<g2, 256>>>(labels);
    k_finalize<<<1, 1>>>((float*)d_out);
}

// round 2
// speedup vs baseline: 1.1339x; 1.1339x over previous
#include <cuda_runtime.h>
#include <cuda_bf16.h>
#include <cstdint>

// Problem constants (fixed shapes)
#define BATCH 2
#define CDIM 128
#define NPIX 65536          // 256*256
#define MCOLS 1024          // NPIX / chunks
#define LAST0 64512         // (chunks-1)*MCOLS
#define NROWBLK 4096        // NPIX/16
#define SCALE_L2 20.6099075f   // 1/(0.07 * ln2)
#define LN2F 0.6931471805599453f

typedef unsigned long long u64;

// ---------------- scratch (device globals: no allocations allowed) ----------
__device__ uint4  g_Apack[BATCH * NROWBLK * 8 * 32];   // 33.5 MB, mma A fragments
__device__ uint4  g_Bpack[BATCH * 16 * 1024];          // 512 KB: [b][it][(nb*4+s2)*32+lane]
__device__ float  g_inv2[BATCH * NPIX];
__device__ float  g_posl2[BATCH * NPIX];               // pos logit in log2 domain
__device__ double g_acc;

// ---------------- helpers ----------------
__device__ __forceinline__ unsigned pack2(float lo, float hi) {
    __nv_bfloat162 h = __floats2bfloat162_rn(lo, hi);
    return *reinterpret_cast<unsigned*>(&h);
}

__device__ __forceinline__ u64 pk(float lo, float hi) {
    u64 r; asm("mov.b64 %0,{%1,%2};" : "=l"(r) : "f"(lo), "f"(hi)); return r;
}
__device__ __forceinline__ u64 bc(float x) {
    u64 r; asm("mov.b64 %0,{%1,%1};" : "=l"(r) : "f"(x)); return r;
}
__device__ __forceinline__ u64 fma2(u64 a, u64 b, u64 c) {
    u64 d; asm("fma.rn.f32x2 %0,%1,%2,%3;" : "=l"(d) : "l"(a), "l"(b), "l"(c)); return d;
}
__device__ __forceinline__ u64 add2(u64 a, u64 b) {
    u64 d; asm("add.rn.f32x2 %0,%1,%2;" : "=l"(d) : "l"(a), "l"(b)); return d;
}

// scalar exp2 (used once per row for pos). Exact at x==0.
__device__ __forceinline__ float exp2p(float x) {
    int   i = __float2int_rn(x);
    float f = x - (float)i;
    float p = 1.3333558146e-3f;
    p = fmaf(p, f, 9.6181291076e-3f);
    p = fmaf(p, f, 5.5504108664e-2f);
    p = fmaf(p, f, 2.4022650696e-1f);
    p = fmaf(p, f, 6.9314718056e-1f);
    p = fmaf(p, f, 1.0f);
    return __int_as_float(__float_as_int(p) + (i << 23));
}

#define CP16(dst, src) asm volatile("cp.async.ca.shared.global [%0],[%1],16;\n" :: "r"(dst), "l"(src))
#define CPCOMMIT()     asm volatile("cp.async.commit_group;\n")
#define CPWAIT0()      asm volatile("cp.async.wait_group 0;\n")

// ---------------- kernel 0: zero accumulator ----------------
__global__ void k_zero() { g_acc = 0.0; }

// ---------------- kernel 1: normalize z1/z2, compute pos (fp32), pack A fragments ----
__global__ void __launch_bounds__(256) k_norm_pack(const float* __restrict__ z1,
                                                   const float* __restrict__ z2) {
    const int b  = blockIdx.y;
    const int p0 = blockIdx.x * 32;
    const int tx = threadIdx.x & 31;   // pixel within tile
    const int ty = threadIdx.x >> 5;   // channel group

    __shared__ float s1[128][33];
    __shared__ float red[3][8][32];
    __shared__ float invsm[32];

    const float* z1b = z1 + (size_t)b * CDIM * NPIX + p0;
    const float* z2b = z2 + (size_t)b * CDIM * NPIX + p0;

    float ss1 = 0.f, ss2 = 0.f, dt = 0.f;
#pragma unroll
    for (int j = 0; j < 16; j++) {
        int c = ty * 16 + j;
        float v1 = z1b[(size_t)c * NPIX + tx];
        float v2 = z2b[(size_t)c * NPIX + tx];
        ss1 = fmaf(v1, v1, ss1);
        ss2 = fmaf(v2, v2, ss2);
        dt  = fmaf(v1, v2, dt);
        s1[c][tx] = v1;
    }
    red[0][ty][tx] = ss1; red[1][ty][tx] = ss2; red[2][ty][tx] = dt;
    __syncthreads();

    if (ty == 0) {
        float a = 0.f, bb = 0.f, d = 0.f;
#pragma unroll
        for (int j = 0; j < 8; j++) { a += red[0][j][tx]; bb += red[1][j][tx]; d += red[2][j][tx]; }
        float inv1 = 1.f / fmaxf(sqrtf(a),  1e-12f);
        float inv2 = 1.f / fmaxf(sqrtf(bb), 1e-12f);
        invsm[tx] = inv1;
        g_inv2 [b * NPIX + p0 + tx] = inv2;
        g_posl2[b * NPIX + p0 + tx] = d * inv1 * inv2 * SCALE_L2;  // pos in log2 domain
    }
    __syncthreads();

    // Pack A into mma fragment order
#pragma unroll
    for (int q = 0; q < 2; q++) {
        int wi   = threadIdx.x + q * 256;
        int rbl  = wi >> 8;
        int rem  = wi & 255;
        int s    = rem >> 5;
        int lane = rem & 31;
        int gid  = lane >> 2, tig = lane & 3;
        int pl   = rbl * 16 + gid;
        int k0   = s * 16 + tig * 2;
        float i1 = invsm[pl], i2 = invsm[pl + 8];
        uint4 o;
        o.x = pack2(s1[k0    ][pl]     * i1, s1[k0 + 1][pl]     * i1);
        o.y = pack2(s1[k0    ][pl + 8] * i2, s1[k0 + 1][pl + 8] * i2);
        o.z = pack2(s1[k0 + 8][pl]     * i1, s1[k0 + 9][pl]     * i1);
        o.w = pack2(s1[k0 + 8][pl + 8] * i2, s1[k0 + 9][pl + 8] * i2);
        int rb = blockIdx.x * 2 + rbl;
        g_Apack[((b * NROWBLK + rb) * 8 + s) * 32 + lane] = o;
    }
}

// ---------------- kernel 2: pack B fragments as uint4 (2 k-steps per entry) --------
// entry [b][it][(nb*4+s2)*32+lane]: .xy = frag for s=2*s2, .zw = frag s=2*s2+1
__global__ void k_packB(const float* __restrict__ z2) {
    int g = blockIdx.x * 256 + threadIdx.x;       // 0..32767
    int b   = g >> 14;
    int r   = g & 16383;
    int it  = r >> 10;
    int idx = r & 1023;
    int nb  = idx >> 7;
    int s2  = (idx >> 5) & 3;
    int lane = idx & 31;
    int gid = lane >> 2, tig = lane & 3;
    int col = it * 64 + nb * 8 + gid;
    int pq  = LAST0 + col;
    float inv = g_inv2[b * NPIX + pq] * SCALE_L2;
    const float* zp = z2 + (size_t)b * CDIM * NPIX + pq;
    int k0 = s2 * 32 + tig * 2;
    uint4 o;
    o.x = pack2(zp[(size_t)(k0     ) * NPIX] * inv, zp[(size_t)(k0 +  1) * NPIX] * inv);
    o.y = pack2(zp[(size_t)(k0 +  8) * NPIX] * inv, zp[(size_t)(k0 +  9) * NPIX] * inv);
    o.z = pack2(zp[(size_t)(k0 + 16) * NPIX] * inv, zp[(size_t)(k0 + 17) * NPIX] * inv);
    o.w = pack2(zp[(size_t)(k0 + 24) * NPIX] * inv, zp[(size_t)(k0 + 25) * NPIX] * inv);
    g_Bpack[g] = o;
}

// ---------------- kernel 3: GEMM (bf16 mma, 2 chains) + packed f32x2 epilogue -------
__global__ void __launch_bounds__(256) k_main(const int* __restrict__ labels) {
    const int b    = blockIdx.y;
    const int row0 = blockIdx.x * 128;
    const int tid  = threadIdx.x;
    const int w    = tid >> 5;
    const int lane = tid & 31;
    const int gid  = lane >> 2, tig = lane & 3;

    __shared__ uint4 Bsm[2][1024];   // double-buffered 16KB tiles
    __shared__ int   labsm[1024];
    __shared__ float warpsum[8];

    // labels of last chunk -> shared (vectorized)
    {
        const uint4* lp = (const uint4*)(labels + b * NPIX + LAST0);
        ((uint4*)labsm)[tid] = lp[tid];
    }

    // A fragments for this warp's 16 rows: 8 x uint4 = 32 regs
    const int rb = blockIdx.x * 8 + w;
    uint4 a[8];
    const uint4* Ap = g_Apack + ((size_t)(b * NROWBLK + rb) * 8) * 32 + lane;
#pragma unroll
    for (int s = 0; s < 8; s++) a[s] = Ap[s * 32];

    const int r0  = row0 + w * 16 + gid;
    const int lr0 = labels[b * NPIX + r0];
    const int lr1 = labels[b * NPIX + r0 + 8];

    // packed constants (uniform across threads)
    const u64 MAG  = bc(12582912.0f);   // 1.5 * 2^23
    const u64 NMAG = bc(-12582912.0f);
    const u64 NONE = bc(-1.0f);
    const u64 C5 = bc(1.3333558146e-3f);
    const u64 C4 = bc(9.6181291076e-3f);
    const u64 C3 = bc(5.5504108664e-2f);
    const u64 C2 = bc(2.4022650696e-1f);
    const u64 C1 = bc(6.9314718056e-1f);
    const u64 ONE = bc(1.0f);

    u64 sxp0 = 0, sxp1 = 0, sep0 = 0, sep1 = 0;

    const uint4* Bp = g_Bpack + b * 16384;

    // prefetch tile 0
    {
        unsigned sd = (unsigned)__cvta_generic_to_shared(&Bsm[0][0]);
#pragma unroll
        for (int i = 0; i < 4; i++)
            CP16(sd + (tid + 256 * i) * 16, Bp + tid + 256 * i);
        CPCOMMIT();
    }

    for (int it = 0; it < 16; it++) {
        const int buf = it & 1;
        CPWAIT0();
        __syncthreads();
        // prefetch next tile into the other buffer (freed by the barrier above)
        if (it < 15) {
            unsigned sd = (unsigned)__cvta_generic_to_shared(&Bsm[buf ^ 1][0]);
            const uint4* src = Bp + (it + 1) * 1024;
#pragma unroll
            for (int i = 0; i < 4; i++)
                CP16(sd + (tid + 256 * i) * 16, src + tid + 256 * i);
            CPCOMMIT();
        }

        const uint4* Bb = &Bsm[buf][0];
#pragma unroll
        for (int nb = 0; nb < 8; nb++) {
            float e0 = 0.f, e1 = 0.f, e2 = 0.f, e3 = 0.f;   // even k-step chain
            float o0 = 0.f, o1 = 0.f, o2 = 0.f, o3 = 0.f;   // odd  k-step chain
#pragma unroll
            for (int s2 = 0; s2 < 4; s2++) {
                uint4 bf = Bb[(nb * 4 + s2) * 32 + lane];
                asm volatile(
                    "mma.sync.aligned.m16n8k16.row.col.f32.bf16.bf16.f32 "
                    "{%0,%1,%2,%3}, {%4,%5,%6,%7}, {%8,%9}, {%0,%1,%2,%3};\n"
                    : "+f"(e0), "+f"(e1), "+f"(e2), "+f"(e3)
                    : "r"(a[2 * s2].x), "r"(a[2 * s2].y), "r"(a[2 * s2].z), "r"(a[2 * s2].w),
                      "r"(bf.x), "r"(bf.y));
                asm volatile(
                    "mma.sync.aligned.m16n8k16.row.col.f32.bf16.bf16.f32 "
                    "{%0,%1,%2,%3}, {%4,%5,%6,%7}, {%8,%9}, {%0,%1,%2,%3};\n"
                    : "+f"(o0), "+f"(o1), "+f"(o2), "+f"(o3)
                    : "r"(a[2 * s2 + 1].x), "r"(a[2 * s2 + 1].y), "r"(a[2 * s2 + 1].z), "r"(a[2 * s2 + 1].w),
                      "r"(bf.z), "r"(bf.w));
            }
            float c0 = e0 + o0, c1 = e1 + o1, c2 = e2 + o2, c3 = e3 + o3;

            // epilogue: mask, then packed sum_x / sum_exp2
            int2 lc = ((const int2*)labsm)[it * 32 + nb * 4 + tig];
            float v0 = (lr0 != lc.x) ? c0 : 0.f;
            float v1 = (lr0 != lc.y) ? c1 : 0.f;
            float v2 = (lr1 != lc.x) ? c2 : 0.f;
            float v3 = (lr1 != lc.y) ? c3 : 0.f;
            u64 P0 = pk(v0, v1), P1 = pk(v2, v3);
            sxp0 = add2(sxp0, P0);
            sxp1 = add2(sxp1, P1);
            // packed exp2: magic round, poly, exponent splice
            {
                u64 t = add2(P0, MAG);
                u64 gg = add2(t, NMAG);
                u64 f = fma2(gg, NONE, P0);
                u64 p = fma2(C5, f, C4);
                p = fma2(p, f, C3); p = fma2(p, f, C2);
                p = fma2(p, f, C1); p = fma2(p, f, ONE);
                unsigned t0, t1, q0, q1;
                asm("mov.b64 {%0,%1},%2;" : "=r"(t0), "=r"(t1) : "l"(t));
                asm("mov.b64 {%0,%1},%2;" : "=r"(q0), "=r"(q1) : "l"(p));
                unsigned r0b = q0 + (t0 << 23), r1b = q1 + (t1 << 23);
                u64 e; asm("mov.b64 %0,{%1,%2};" : "=l"(e) : "r"(r0b), "r"(r1b));
                sep0 = add2(sep0, e);
            }
            {
                u64 t = add2(P1, MAG);
                u64 gg = add2(t, NMAG);
                u64 f = fma2(gg, NONE, P1);
                u64 p = fma2(C5, f, C4);
                p = fma2(p, f, C3); p = fma2(p, f, C2);
                p = fma2(p, f, C1); p = fma2(p, f, ONE);
                unsigned t0, t1, q0, q1;
                asm("mov.b64 {%0,%1},%2;" : "=r"(t0), "=r"(t1) : "l"(t));
                asm("mov.b64 {%0,%1},%2;" : "=r"(q0), "=r"(q1) : "l"(p));
                unsigned r0b = q0 + (t0 << 23), r1b = q1 + (t1 << 23);
                u64 e; asm("mov.b64 %0,{%1,%2};" : "=l"(e) : "r"(r0b), "r"(r1b));
                sep1 = add2(sep1, e);
            }
        }
        __syncthreads();   // all reads of buf done before it gets overwritten next iter
    }

    // unpack packed accumulators
    float sa, sb;
    asm("mov.b64 {%0,%1},%2;" : "=f"(sa), "=f"(sb) : "l"(sxp0)); float sx0 = sa + sb;
    asm("mov.b64 {%0,%1},%2;" : "=f"(sa), "=f"(sb) : "l"(sep0)); float se0 = sa + sb;
    asm("mov.b64 {%0,%1},%2;" : "=f"(sa), "=f"(sb) : "l"(sxp1)); float sx1 = sa + sb;
    asm("mov.b64 {%0,%1},%2;" : "=f"(sa), "=f"(sb) : "l"(sep1)); float se1 = sa + sb;

    // reduce across the 4 lanes sharing a row (tig dimension)
    sx0 += __shfl_xor_sync(~0u, sx0, 1);  sx0 += __shfl_xor_sync(~0u, sx0, 2);
    se0 += __shfl_xor_sync(~0u, se0, 1);  se0 += __shfl_xor_sync(~0u, se0, 2);
    sx1 += __shfl_xor_sync(~0u, sx1, 1);  sx1 += __shfl_xor_sync(~0u, sx1, 2);
    se1 += __shfl_xor_sync(~0u, se1, 1);  se1 += __shfl_xor_sync(~0u, se1, 2);

    float loss = 0.f;
    if (tig == 0) {
        float p0 = g_posl2[b * NPIX + r0];
        float p1 = g_posl2[b * NPIX + r0 + 8];
        float t0 = se0 + exp2p(p0), x0 = sx0 + p0;
        float t1 = se1 + exp2p(p1), x1 = sx1 + p1;
        loss = LN2F * ((__log2f(t0) - x0 * (1.0f / 1025.0f)) +
                       (__log2f(t1) - x1 * (1.0f / 1025.0f)));
    }
#pragma unroll
    for (int o = 16; o; o >>= 1) loss += __shfl_xor_sync(~0u, loss, o);
    if (lane == 0) warpsum[w] = loss;
    __syncthreads();
    if (tid == 0) {
        float t = 0.f;
#pragma unroll
        for (int i = 0; i < 8; i++) t += warpsum[i];
        atomicAdd(&g_acc, (double)t);
    }
}

// ---------------- kernel 4: finalize ----------------
__global__ void k_finalize(float* out) {
    out[0] = (float)(g_acc / (double)(BATCH * NPIX));
}

// ---------------- launch ----------------
extern "C" void kernel_launch(void* const* d_in, const int* in_sizes, int n_in,
                              void* d_out, int out_size) {
    const float* z1     = (const float*)d_in[0];
    const float* z2     = (const float*)d_in[1];
    const int*   labels = (const int*)d_in[2];
    (void)in_sizes; (void)n_in; (void)out_size;

    k_zero<<<1, 1>>>();
    dim3 g1(NPIX / 32, BATCH);
    k_norm_pack<<<g1, 256>>>(z1, z2);
    k_packB<<<128, 256>>>(z2);
    dim3 g2(NPIX / 128, BATCH);
    k_main<<<g2, 256>>>(labels);
    k_finalize<<<1, 1>>>((float*)d_out);
}